// round 8
// baseline (speedup 1.0000x reference)
#include <cuda_runtime.h>
#include <math.h>

#define BN    2
#define NPTS  8192
#define KNN   16
#define CIN   32
#define EIN   67
#define HID   128
#define COUT  64
#define TOT   (BN*NPTS)
#define FULLM 0xffffffffu
#define FMAX  3.402823466e38f

// Grid for KNN
#define NC      31
#define NCELLS  (NC*NC*NC)           // 29791
#define NCELL2  (2*NCELLS)           // 59582
#define ORG     (-4.65f)
#define CSZ     0.3f
#define INVH    (1.0f/0.3f)
#define BUFCAP  1024

// Scratch (no allocations allowed)
__device__ int    g_idx[TOT*KNN];
__device__ float  g_mid[TOT*COUT];
__device__ float4 g_vert4[TOT];
__device__ float  g_q[TOT*HID];
__device__ float  g_p[TOT*HID];
__device__ int    g_pcell[TOT];
__device__ int    g_ccount[NCELL2];
__device__ int    g_cstart[NCELL2];
__device__ int    g_cend[NCELL2];
__device__ int    g_ccur[NCELL2];
__device__ int    g_cursor;
__device__ float4 g_spos[TOT];
__device__ int    g_sidx[TOT];

// ---------------------------------------------------------------------------
__global__ void prep_kernel(const float* __restrict__ verts) {
    int i = blockIdx.x * blockDim.x + threadIdx.x;
    if (i < TOT) {
        float x = verts[i*3+0], y = verts[i*3+1], z = verts[i*3+2];
        g_vert4[i] = make_float4(x, y, z, x*x + y*y + z*z);
    }
}

__global__ void zero_kernel() {
    int i = blockIdx.x * blockDim.x + threadIdx.x;
    if (i < NCELL2) g_ccount[i] = 0;
    if (i == 0) g_cursor = 0;
}

__device__ __forceinline__ int clampi(int v, int lo, int hi) {
    return v < lo ? lo : (v > hi ? hi : v);
}

__global__ void bin_kernel() {
    int i = blockIdx.x * blockDim.x + threadIdx.x;
    if (i >= TOT) return;
    float4 v = g_vert4[i];
    int cx = clampi((int)floorf((v.x - ORG) * INVH), 0, NC-1);
    int cy = clampi((int)floorf((v.y - ORG) * INVH), 0, NC-1);
    int cz = clampi((int)floorf((v.z - ORG) * INVH), 0, NC-1);
    int cid = (i >> 13) * NCELLS + (cx*NC + cy)*NC + cz;
    g_pcell[i] = cid;
    atomicAdd(&g_ccount[cid], 1);
}

// Segment allocation via atomic cursor — replaces the 90us single-block scan.
// Cell segment ORDER varies run-to-run but stored content (original indices)
// makes the final output value-identical.
__global__ void alloc_kernel() {
    int i = blockIdx.x * blockDim.x + threadIdx.x;
    if (i >= NCELL2) return;
    int c = g_ccount[i];
    if (c > 0) {
        int s = atomicAdd(&g_cursor, c);
        g_cstart[i] = s;
        g_ccur[i]   = s;
        g_cend[i]   = s + c;
    } else {
        g_cstart[i] = 0;
        g_cend[i]   = 0;
    }
}

__global__ void scatter_kernel() {
    int i = blockIdx.x * blockDim.x + threadIdx.x;
    if (i >= TOT) return;
    int cid  = g_pcell[i];
    int slot = atomicAdd(&g_ccur[cid], 1);
    g_spos[slot] = g_vert4[i];
    g_sidx[slot] = i;
}

// ---------------------------------------------------------------------------
// Process cnt buffered candidates through the warp's ascending lane-sorted
// best-32 queue (same machinery as the proven brute-force version).
// ---------------------------------------------------------------------------
__device__ __forceinline__ void qprocess(const int* __restrict__ buf, int cnt,
                                         float& key, int& sid, float& th,
                                         float4 qv, int lane) {
    for (int i = 0; i < cnt; i += 32) {
        int p = i + lane;
        int sx = (p < cnt) ? buf[p] : -1;
        float d = FMAX;
        if (sx >= 0) {
            float4 c = g_spos[sx];
            float dot = fmaf(qv.x, c.x, fmaf(qv.y, c.y, qv.z*c.z));
            d = fmaf(-2.0f, dot, qv.w + c.w);
        }
        unsigned mask = __ballot_sync(FULLM, d < th);
        while (mask) {
            int src = __ffs(mask) - 1;
            mask &= mask - 1;
            float v  = __shfl_sync(FULLM, d,  src);
            int   vi = __shfl_sync(FULLM, sx, src);
            if (v < th) {
                float pk = __shfl_up_sync(FULLM, key, 1);
                int   pi = __shfl_up_sync(FULLM, sid, 1);
                if (v < key) {
                    if (lane > 0 && v < pk) { key = pk; sid = pi; }
                    else                    { key = v;  sid = vi; }
                }
                th = __shfl_sync(FULLM, key, 15);
            }
        }
    }
}

// ---------------------------------------------------------------------------
// Grid KNN: warp per query, expanding Chebyshev shells, CELL-BOX PRUNING
// (skip cells whose min squared distance >= th), exact stop bound.
// 16 cells per enumeration batch -> total <= 1024 = BUFCAP (no overflow).
// ---------------------------------------------------------------------------
__global__ void __launch_bounds__(256) knn_grid_kernel() {
    extern __shared__ int sbuf[];          // 8 warps * BUFCAP
    int tid  = threadIdx.x;
    int lane = tid & 31;
    int w    = tid >> 5;
    int* wbuf = sbuf + w * BUFCAP;

    int gq = blockIdx.x * 8 + w;
    int cellbase = (gq >> 13) * NCELLS;

    float4 qv = g_vert4[gq];
    int cx = clampi((int)floorf((qv.x - ORG) * INVH), 0, NC-1);
    int cy = clampi((int)floorf((qv.y - ORG) * INVH), 0, NC-1);
    int cz = clampi((int)floorf((qv.z - ORG) * INVH), 0, NC-1);

    float key = FMAX, th = FMAX;
    int   sid = -1;

    int s = 1;
    for (;;) {
        int side = 2*s + 1;
        int tot3 = side * side * side;
        int cnt  = 0;
        for (int ci0 = 0; ci0 < tot3; ci0 += 16) {
            int ci = ci0 + lane;
            int ccount = 0, cstart = 0;
            if (lane < 16 && ci < tot3) {
                int dz = ci % side;
                int t2 = ci / side;
                int dy = t2 % side;
                int dx = t2 / side;
                dx -= s; dy -= s; dz -= s;
                int adx = abs(dx), ady = abs(dy), adz = abs(dz);
                int cheb = max(adx, max(ady, adz));
                int X = cx + dx, Y = cy + dy, Z = cz + dz;
                bool on = (s == 1 || cheb == s) &&
                          X >= 0 && X < NC && Y >= 0 && Y < NC && Z >= 0 && Z < NC;
                if (on) {
                    // cell-box min distance pruning (safe: inserts need d < th)
                    float lox = ORG + X * CSZ, hix = lox + CSZ;
                    float loy = ORG + Y * CSZ, hiy = loy + CSZ;
                    float loz = ORG + Z * CSZ, hiz = loz + CSZ;
                    float ddx = fmaxf(0.f, fmaxf(lox - qv.x, qv.x - hix));
                    float ddy = fmaxf(0.f, fmaxf(loy - qv.y, qv.y - hiy));
                    float ddz = fmaxf(0.f, fmaxf(loz - qv.z, qv.z - hiz));
                    float mind = fmaf(ddx, ddx, fmaf(ddy, ddy, ddz*ddz));
                    if (mind < th) {
                        int cid = cellbase + (X*NC + Y)*NC + Z;
                        cstart = g_cstart[cid];
                        ccount = g_cend[cid] - cstart;
                    }
                }
            }
            // warp exclusive scan of ccount
            int inc = ccount;
#pragma unroll
            for (int d = 1; d < 32; d <<= 1) {
                int v = __shfl_up_sync(FULLM, inc, d);
                if (lane >= d) inc += v;
            }
            int total = __shfl_sync(FULLM, inc, 31);
            int off   = inc - ccount;
            if (cnt + total > BUFCAP) {
                __syncwarp();
                qprocess(wbuf, cnt, key, sid, th, qv, lane);
                __syncwarp();
                cnt = 0;
            }
            for (int k2 = 0; k2 < ccount; k2++) wbuf[cnt + off + k2] = cstart + k2;
            __syncwarp();
            cnt += total;
        }
        __syncwarp();
        qprocess(wbuf, cnt, key, sid, th, qv, lane);
        __syncwarp();

        // exact stop bound: any unvisited point is at distance >= gmin
        float gxl = (cx - s <= 0)      ? FMAX : qv.x - (ORG + (cx - s) * CSZ);
        float gxh = (cx + s >= NC - 1) ? FMAX : (ORG + (cx + s + 1) * CSZ) - qv.x;
        float gyl = (cy - s <= 0)      ? FMAX : qv.y - (ORG + (cy - s) * CSZ);
        float gyh = (cy + s >= NC - 1) ? FMAX : (ORG + (cy + s + 1) * CSZ) - qv.y;
        float gzl = (cz - s <= 0)      ? FMAX : qv.z - (ORG + (cz - s) * CSZ);
        float gzh = (cz + s >= NC - 1) ? FMAX : (ORG + (cz + s + 1) * CSZ) - qv.z;
        float gmin = fminf(fminf(fminf(gxl, gxh), fminf(gyl, gyh)), fminf(gzl, gzh));
        if (gmin > 1e37f) break;                          // grid fully covered
        if (th < 1e37f && gmin > 0.0f && th <= gmin*gmin) break;
        s++;
    }

    if (lane < KNN) g_idx[gq*KNN + lane] = g_sidx[sid];
}

// ---------------------------------------------------------------------------
// Precompute Q[n], P[n]: warp per point, W1 staged in smem.
// ---------------------------------------------------------------------------
__global__ void __launch_bounds__(256) precomp_kernel(
    const float* __restrict__ verts, const float* __restrict__ feat,
    const float* __restrict__ W1, const float* __restrict__ b1)
{
    __shared__ float sW1[EIN*HID];
    int tid = threadIdx.x, lane = tid & 31, w = tid >> 5;
    for (int e = tid; e < EIN*HID; e += 256) sW1[e] = W1[e];
    __syncthreads();

    int p = blockIdx.x * 8 + w;
    float4 f4 = make_float4(0.f,0.f,0.f,0.f);
    if (lane < 8) f4 = *(const float4*)&feat[p*CIN + lane*4];
    float vx = verts[p*3+0], vy = verts[p*3+1], vz = verts[p*3+2];

    int c = lane*4;
    float4 q  = make_float4(0.f,0.f,0.f,0.f);
    float4 pp = *(const float4*)&b1[c];

#pragma unroll
    for (int src = 0; src < 8; src++) {
        float fx = __shfl_sync(FULLM, f4.x, src);
        float fy = __shfl_sync(FULLM, f4.y, src);
        float fz = __shfl_sync(FULLM, f4.z, src);
        float fw = __shfl_sync(FULLM, f4.w, src);
        float fv[4] = {fx, fy, fz, fw};
        int k0 = src*4;
#pragma unroll
        for (int kk = 0; kk < 4; kk++) {
            int k = k0 + kk;
            float4 wa = *(const float4*)&sW1[k*HID + c];
            float4 wb = *(const float4*)&sW1[(CIN + k)*HID + c];
            q.x  = fmaf(fv[kk], wa.x, q.x);  q.y  = fmaf(fv[kk], wa.y, q.y);
            q.z  = fmaf(fv[kk], wa.z, q.z);  q.w  = fmaf(fv[kk], wa.w, q.w);
            pp.x = fmaf(fv[kk], wb.x, pp.x); pp.y = fmaf(fv[kk], wb.y, pp.y);
            pp.z = fmaf(fv[kk], wb.z, pp.z); pp.w = fmaf(fv[kk], wb.w, pp.w);
        }
    }
    float vv[3] = {vx, vy, vz};
#pragma unroll
    for (int k = 0; k < 3; k++) {
        float4 wc = *(const float4*)&sW1[(2*CIN + k)*HID + c];
        q.x  = fmaf(vv[k],  wc.x, q.x);  q.y  = fmaf(vv[k],  wc.y, q.y);
        q.z  = fmaf(vv[k],  wc.z, q.z);  q.w  = fmaf(vv[k],  wc.w, q.w);
        pp.x = fmaf(-vv[k], wc.x, pp.x); pp.y = fmaf(-vv[k], wc.y, pp.y);
        pp.z = fmaf(-vv[k], wc.z, pp.z); pp.w = fmaf(-vv[k], wc.w, pp.w);
    }
    *(float4*)&g_q[p*HID + c] = q;
    *(float4*)&g_p[p*HID + c] = pp;
}

// ---------------------------------------------------------------------------
__device__ __forceinline__ float gelu_fast(float x) {
    float z2 = 1.5957691216057308f * fmaf(0.044715f * x * x, x, x);
    float e  = __expf(z2);
    float r  = __fdividef(1.0f, e + 1.0f);
    return x - x * r;
}

// ---------------------------------------------------------------------------
// Edge kernel: warp per point (256 threads — fastest measured config).
// ---------------------------------------------------------------------------
__global__ void __launch_bounds__(256) edge_kernel(
    const float* __restrict__ g1, const float* __restrict__ be1,
    const float* __restrict__ W2, const float* __restrict__ b2)
{
    __shared__ float sW2[HID*COUT];
    int tid = threadIdx.x, lane = tid & 31, w = tid >> 5;
    for (int e = tid; e < HID*COUT; e += 256) sW2[e] = W2[e];
    __syncthreads();

    int p = blockIdx.x * 8 + w;
    int myidx = (lane < KNN) ? g_idx[p*KNN + lane] : 0;
    int c = lane * 4;

    float4 P4  = *(const float4*)&g_p[p*HID + c];
    float4 g1v = *(const float4*)&g1[c];
    float4 bev = *(const float4*)&be1[c];

    float4 accG = make_float4(0.f,0.f,0.f,0.f);

    int nb0 = __shfl_sync(FULLM, myidx, 0);
    int nb1 = __shfl_sync(FULLM, myidx, 1);
    float4 qa = __ldg((const float4*)&g_q[nb0*HID + c]);
    float4 qb = __ldg((const float4*)&g_q[nb1*HID + c]);

#pragma unroll
    for (int n = 0; n < KNN; n += 2) {
        float4 h0, h1;
        h0.x = qa.x + P4.x; h0.y = qa.y + P4.y; h0.z = qa.z + P4.z; h0.w = qa.w + P4.w;
        h1.x = qb.x + P4.x; h1.y = qb.y + P4.y; h1.z = qb.z + P4.z; h1.w = qb.w + P4.w;
        if (n + 2 < KNN) {
            int na  = __shfl_sync(FULLM, myidx, n+2);
            int nbx = __shfl_sync(FULLM, myidx, n+3);
            qa = __ldg((const float4*)&g_q[na*HID + c]);
            qb = __ldg((const float4*)&g_q[nbx*HID + c]);
        }
        float s0  = (h0.x + h0.y) + (h0.z + h0.w);
        float s20 = fmaf(h0.x,h0.x, fmaf(h0.y,h0.y, fmaf(h0.z,h0.z, h0.w*h0.w)));
        float s1  = (h1.x + h1.y) + (h1.z + h1.w);
        float s21 = fmaf(h1.x,h1.x, fmaf(h1.y,h1.y, fmaf(h1.z,h1.z, h1.w*h1.w)));
#pragma unroll
        for (int off = 16; off; off >>= 1) {
            s0  += __shfl_xor_sync(FULLM, s0,  off);
            s1  += __shfl_xor_sync(FULLM, s1,  off);
            s20 += __shfl_xor_sync(FULLM, s20, off);
            s21 += __shfl_xor_sync(FULLM, s21, off);
        }
        float mu0  = s0  * (1.f/HID);
        float var0 = s20 * (1.f/HID) - mu0*mu0;
        float rs0  = rsqrtf(var0 + 1e-5f);
        float mu1  = s1  * (1.f/HID);
        float var1 = s21 * (1.f/HID) - mu1*mu1;
        float rs1  = rsqrtf(var1 + 1e-5f);
        accG.x += gelu_fast(fmaf((h0.x - mu0)*rs0, g1v.x, bev.x));
        accG.y += gelu_fast(fmaf((h0.y - mu0)*rs0, g1v.y, bev.y));
        accG.z += gelu_fast(fmaf((h0.z - mu0)*rs0, g1v.z, bev.z));
        accG.w += gelu_fast(fmaf((h0.w - mu0)*rs0, g1v.w, bev.w));
        accG.x += gelu_fast(fmaf((h1.x - mu1)*rs1, g1v.x, bev.x));
        accG.y += gelu_fast(fmaf((h1.y - mu1)*rs1, g1v.y, bev.y));
        accG.z += gelu_fast(fmaf((h1.z - mu1)*rs1, g1v.z, bev.z));
        accG.w += gelu_fast(fmaf((h1.w - mu1)*rs1, g1v.w, bev.w));
    }
    accG.x *= (1.f/KNN); accG.y *= (1.f/KNN);
    accG.z *= (1.f/KNN); accG.w *= (1.f/KNN);

    float m0 = __ldg(&b2[lane]);
    float m1 = __ldg(&b2[lane + 32]);
#pragma unroll
    for (int src = 0; src < 32; src++) {
        float gx = __shfl_sync(FULLM, accG.x, src);
        float gy = __shfl_sync(FULLM, accG.y, src);
        float gz = __shfl_sync(FULLM, accG.z, src);
        float gw = __shfl_sync(FULLM, accG.w, src);
        int k0 = src * 4;
        m0 = fmaf(gx, sW2[(k0+0)*COUT + lane], m0);
        m0 = fmaf(gy, sW2[(k0+1)*COUT + lane], m0);
        m0 = fmaf(gz, sW2[(k0+2)*COUT + lane], m0);
        m0 = fmaf(gw, sW2[(k0+3)*COUT + lane], m0);
        m1 = fmaf(gx, sW2[(k0+0)*COUT + lane + 32], m1);
        m1 = fmaf(gy, sW2[(k0+1)*COUT + lane + 32], m1);
        m1 = fmaf(gz, sW2[(k0+2)*COUT + lane + 32], m1);
        m1 = fmaf(gw, sW2[(k0+3)*COUT + lane + 32], m1);
    }
    g_mid[p*COUT + lane]      = m0;
    g_mid[p*COUT + lane + 32] = m1;
}

// ---------------------------------------------------------------------------
// MLP2 fused: 64 points per block, grid 256.
// ---------------------------------------------------------------------------
#define M2PTS 64
#define SMEM2_FLOATS (COUT*M2PTS + COUT*HID + HID*COUT)  // 20480

__global__ void __launch_bounds__(256, 2) mlp2_kernel(
    const float* __restrict__ Wo1, const float* __restrict__ bo1,
    const float* __restrict__ go,  const float* __restrict__ beo,
    const float* __restrict__ Wo2, const float* __restrict__ bo2,
    float* __restrict__ out)
{
    extern __shared__ float sm[];
    float* sAt  = sm;
    float* sWo1 = sm + COUT*M2PTS;
    float* sH   = sm;                          // aliases sAt+sWo1
    float* sWo2 = sm + COUT*M2PTS + COUT*HID;

    int tid = threadIdx.x;
    int r0  = blockIdx.x * M2PTS;

    for (int e = tid; e < COUT*HID; e += 256) sWo1[e] = Wo1[e];
    for (int e = tid; e < HID*COUT; e += 256) sWo2[e] = Wo2[e];
    for (int e = tid; e < COUT*M2PTS; e += 256) {
        int r = e & (M2PTS-1), k = e >> 6;
        sAt[k*M2PTS + r] = g_mid[(r0 + r)*COUT + k];
    }
    __syncthreads();

    int tx = tid & 15, ty = tid >> 4;

    float acc[4][8];
#pragma unroll
    for (int i = 0; i < 4; i++)
#pragma unroll
        for (int j = 0; j < 8; j++) acc[i][j] = 0.f;

    for (int k = 0; k < COUT; k++) {
        float4 a4 = *(const float4*)&sAt[k*M2PTS + ty*4];
        float4 c0 = *(const float4*)&sWo1[k*HID + tx*8];
        float4 c1 = *(const float4*)&sWo1[k*HID + tx*8 + 4];
        float a[4] = {a4.x,a4.y,a4.z,a4.w};
        float wv[8] = {c0.x,c0.y,c0.z,c0.w,c1.x,c1.y,c1.z,c1.w};
#pragma unroll
        for (int i = 0; i < 4; i++)
#pragma unroll
            for (int j = 0; j < 8; j++)
                acc[i][j] = fmaf(a[i], wv[j], acc[i][j]);
    }

    __syncthreads();

    float b1j[8], gj[8], bej[8];
#pragma unroll
    for (int j = 0; j < 8; j++) {
        int col = tx*8 + j;
        b1j[j] = bo1[col]; gj[j] = go[col]; bej[j] = beo[col];
    }
#pragma unroll
    for (int i = 0; i < 4; i++) {
        float ps = 0.f, ps2 = 0.f;
#pragma unroll
        for (int j = 0; j < 8; j++) {
            float h = acc[i][j] + b1j[j];
            acc[i][j] = h;
            ps += h; ps2 = fmaf(h, h, ps2);
        }
#pragma unroll
        for (int off = 8; off; off >>= 1) {
            ps  += __shfl_xor_sync(FULLM, ps,  off);
            ps2 += __shfl_xor_sync(FULLM, ps2, off);
        }
        float mu  = ps  * (1.f/HID);
        float var = ps2 * (1.f/HID) - mu*mu;
        float rs  = rsqrtf(var + 1e-5f);
        float o[8];
#pragma unroll
        for (int j = 0; j < 8; j++)
            o[j] = gelu_fast(fmaf((acc[i][j] - mu)*rs, gj[j], bej[j]));
        int row = ty*4 + i;
        *(float4*)&sH[row*132 + tx*8]     = make_float4(o[0],o[1],o[2],o[3]);
        *(float4*)&sH[row*132 + tx*8 + 4] = make_float4(o[4],o[5],o[6],o[7]);
    }
    __syncthreads();

    float acc2[4][4];
#pragma unroll
    for (int i = 0; i < 4; i++)
#pragma unroll
        for (int j = 0; j < 4; j++) acc2[i][j] = 0.f;

    for (int k = 0; k < HID; k += 4) {
        float4 w0 = *(const float4*)&sWo2[(k+0)*COUT + tx*4];
        float4 w1 = *(const float4*)&sWo2[(k+1)*COUT + tx*4];
        float4 w2 = *(const float4*)&sWo2[(k+2)*COUT + tx*4];
        float4 w3 = *(const float4*)&sWo2[(k+3)*COUT + tx*4];
#pragma unroll
        for (int i = 0; i < 4; i++) {
            float4 av = *(const float4*)&sH[(ty*4+i)*132 + k];
            acc2[i][0] = fmaf(av.x, w0.x, fmaf(av.y, w1.x, fmaf(av.z, w2.x, fmaf(av.w, w3.x, acc2[i][0]))));
            acc2[i][1] = fmaf(av.x, w0.y, fmaf(av.y, w1.y, fmaf(av.z, w2.y, fmaf(av.w, w3.y, acc2[i][1]))));
            acc2[i][2] = fmaf(av.x, w0.z, fmaf(av.y, w1.z, fmaf(av.z, w2.z, fmaf(av.w, w3.z, acc2[i][2]))));
            acc2[i][3] = fmaf(av.x, w0.w, fmaf(av.y, w1.w, fmaf(av.z, w2.w, fmaf(av.w, w3.w, acc2[i][3]))));
        }
    }

    float b2j[4];
#pragma unroll
    for (int j = 0; j < 4; j++) b2j[j] = bo2[tx*4 + j];
#pragma unroll
    for (int i = 0; i < 4; i++) {
        int row = r0 + ty*4 + i;
#pragma unroll
        for (int j = 0; j < 4; j++)
            out[row*COUT + tx*4 + j] = acc2[i][j] + b2j[j];
    }
}

// ---------------------------------------------------------------------------
extern "C" void kernel_launch(void* const* d_in, const int* in_sizes, int n_in,
                              void* d_out, int out_size) {
    const float* verts = (const float*)d_in[0];
    const float* feat  = (const float*)d_in[1];
    const float* W1    = (const float*)d_in[2];
    const float* b1    = (const float*)d_in[3];
    const float* g1    = (const float*)d_in[4];
    const float* be1   = (const float*)d_in[5];
    const float* W2    = (const float*)d_in[6];
    const float* b2    = (const float*)d_in[7];
    const float* Wo1   = (const float*)d_in[8];
    const float* bo1   = (const float*)d_in[9];
    const float* go    = (const float*)d_in[10];
    const float* beo   = (const float*)d_in[11];
    const float* Wo2   = (const float*)d_in[12];
    const float* bo2   = (const float*)d_in[13];
    float* out = (float*)d_out;

    const int smem2   = SMEM2_FLOATS * 4;       // 81920
    const int smemKnn = 8 * BUFCAP * 4;         // 32768
    cudaFuncSetAttribute(mlp2_kernel, cudaFuncAttributeMaxDynamicSharedMemorySize, smem2);
    cudaFuncSetAttribute(knn_grid_kernel, cudaFuncAttributeMaxDynamicSharedMemorySize, smemKnn);

    prep_kernel<<<(TOT + 255)/256, 256>>>(verts);
    zero_kernel<<<(NCELL2 + 255)/256, 256>>>();
    bin_kernel<<<(TOT + 255)/256, 256>>>();
    alloc_kernel<<<(NCELL2 + 255)/256, 256>>>();
    scatter_kernel<<<(TOT + 255)/256, 256>>>();
    knn_grid_kernel<<<TOT/8, 256, smemKnn>>>();
    precomp_kernel<<<TOT/8, 256>>>(verts, feat, W1, b1);
    edge_kernel<<<TOT/8, 256>>>(g1, be1, W2, b2);
    mlp2_kernel<<<TOT/M2PTS, 256, smem2>>>(Wo1, bo1, go, beo, Wo2, bo2, out);
}

// round 9
// speedup vs baseline: 1.6798x; 1.6798x over previous
#include <cuda_runtime.h>
#include <math.h>

#define BN   2
#define NPTS 8192
#define KNN  16
#define CIN  32
#define EIN  67      // 32 + 32 + 3
#define HID  128
#define COUT 64
#define TOT  (BN*NPTS)
#define FULLM 0xffffffffu

// Scratch (no allocations allowed)
__device__ int    g_idx[TOT*KNN];          // GLOBAL neighbor indices
__device__ float  g_mid[TOT*COUT];
__device__ float4 g_vert4[TOT];
__device__ float  g_q[TOT*HID];            // Q[n] = feat@W1a + vert@W1c
__device__ float  g_p[TOT*HID];            // P[n] = feat@W1b + b1 - vert@W1c

// ---------------------------------------------------------------------------
__global__ void prep_kernel(const float* __restrict__ verts) {
    int i = blockIdx.x * blockDim.x + threadIdx.x;
    if (i < TOT) {
        float x = verts[i*3+0], y = verts[i*3+1], z = verts[i*3+2];
        g_vert4[i] = make_float4(x, y, z, x*x + y*y + z*z);
    }
}

// ---------------------------------------------------------------------------
// KNN: one warp handles TWO queries. Ascending lane-sorted best-32 queue per
// query. THRESHOLD IS FROZEN PER BATCH: the queue insert is a no-op for any
// value >= current max, so the queue always contains the true best-32 seen --
// th is purely a work filter and may be stale. Freezing it removes the
// dependent th-broadcast from every insert (chain 80 -> ~35 cyc).
// ---------------------------------------------------------------------------
__global__ void __launch_bounds__(256) knn_kernel() {
    int tid  = threadIdx.x;
    int lane = tid & 31;
    int w    = tid >> 5;
    int qg   = (blockIdx.x * 8 + w) * 2;   // first of 2 consecutive queries
    int b    = qg >> 13;
    int base = b * NPTS;
    int q0   = qg & (NPTS - 1);

    float qx[2], qy[2], qz[2], qs[2];
#pragma unroll
    for (int r = 0; r < 2; r++) {
        float4 qv = g_vert4[base + q0 + r];
        qx[r] = qv.x; qy[r] = qv.y; qz[r] = qv.z; qs[r] = qv.w;
    }

    float key[2];
    int   idx[2];
#pragma unroll
    for (int r = 0; r < 2; r++) { key[r] = 3.4e38f; idx[r] = 0; }

#pragma unroll 2
    for (int i = 0; i < NPTS/32; i++) {
        float4 c = g_vert4[base + i*32 + lane];
        float d[2];
#pragma unroll
        for (int r = 0; r < 2; r++) {
            float dot = fmaf(qx[r], c.x, fmaf(qy[r], c.y, qz[r]*c.z));
            d[r] = fmaf(-2.0f, dot, qs[r] + c.w);
        }
#pragma unroll
        for (int r = 0; r < 2; r++) {
            // batch-frozen threshold (16th best at batch start)
            float thb = __shfl_sync(FULLM, key[r], 15);
            unsigned mask = __ballot_sync(FULLM, d[r] < thb);
            while (mask) {
                int src = __ffs(mask) - 1;
                mask &= mask - 1;
                float v  = __shfl_sync(FULLM, d[r], src);
                int   vi = i*32 + src;
                // unconditional sorted insert (no-op if v >= all keys)
                float pk = __shfl_up_sync(FULLM, key[r], 1);
                int   pi = __shfl_up_sync(FULLM, idx[r], 1);
                if (v < key[r]) {
                    if (lane > 0 && v < pk) { key[r] = pk; idx[r] = pi; }
                    else                    { key[r] = v;  idx[r] = vi; }
                }
            }
        }
    }

    if (lane < KNN) {
#pragma unroll
        for (int r = 0; r < 2; r++)
            g_idx[(base + q0 + r)*KNN + lane] = base + idx[r];
    }
}

// ---------------------------------------------------------------------------
// Precompute Q[n], P[n]: warp per point, W1 staged in smem.
// ---------------------------------------------------------------------------
__global__ void __launch_bounds__(256) precomp_kernel(
    const float* __restrict__ verts, const float* __restrict__ feat,
    const float* __restrict__ W1, const float* __restrict__ b1)
{
    __shared__ float sW1[EIN*HID];   // 34.3KB
    int tid = threadIdx.x, lane = tid & 31, w = tid >> 5;
    for (int e = tid; e < EIN*HID; e += 256) sW1[e] = W1[e];
    __syncthreads();

    int p = blockIdx.x * 8 + w;
    float4 f4 = make_float4(0.f,0.f,0.f,0.f);
    if (lane < 8) f4 = *(const float4*)&feat[p*CIN + lane*4];
    float vx = verts[p*3+0], vy = verts[p*3+1], vz = verts[p*3+2];

    int c = lane*4;
    float4 q  = make_float4(0.f,0.f,0.f,0.f);
    float4 pp = *(const float4*)&b1[c];

#pragma unroll
    for (int src = 0; src < 8; src++) {
        float fx = __shfl_sync(FULLM, f4.x, src);
        float fy = __shfl_sync(FULLM, f4.y, src);
        float fz = __shfl_sync(FULLM, f4.z, src);
        float fw = __shfl_sync(FULLM, f4.w, src);
        float fv[4] = {fx, fy, fz, fw};
        int k0 = src*4;
#pragma unroll
        for (int kk = 0; kk < 4; kk++) {
            int k = k0 + kk;
            float4 wa = *(const float4*)&sW1[k*HID + c];          // W1a row k
            float4 wb = *(const float4*)&sW1[(CIN + k)*HID + c];  // W1b row k
            q.x  = fmaf(fv[kk], wa.x, q.x);  q.y  = fmaf(fv[kk], wa.y, q.y);
            q.z  = fmaf(fv[kk], wa.z, q.z);  q.w  = fmaf(fv[kk], wa.w, q.w);
            pp.x = fmaf(fv[kk], wb.x, pp.x); pp.y = fmaf(fv[kk], wb.y, pp.y);
            pp.z = fmaf(fv[kk], wb.z, pp.z); pp.w = fmaf(fv[kk], wb.w, pp.w);
        }
    }
    float vv[3] = {vx, vy, vz};
#pragma unroll
    for (int k = 0; k < 3; k++) {
        float4 wc = *(const float4*)&sW1[(2*CIN + k)*HID + c];
        q.x  = fmaf(vv[k],  wc.x, q.x);  q.y  = fmaf(vv[k],  wc.y, q.y);
        q.z  = fmaf(vv[k],  wc.z, q.z);  q.w  = fmaf(vv[k],  wc.w, q.w);
        pp.x = fmaf(-vv[k], wc.x, pp.x); pp.y = fmaf(-vv[k], wc.y, pp.y);
        pp.z = fmaf(-vv[k], wc.z, pp.z); pp.w = fmaf(-vv[k], wc.w, pp.w);
    }
    *(float4*)&g_q[p*HID + c] = q;
    *(float4*)&g_p[p*HID + c] = pp;
}

// ---------------------------------------------------------------------------
__device__ __forceinline__ float gelu_fast(float x) {
    float z2 = 1.5957691216057308f * fmaf(0.044715f * x * x, x, x);
    float e  = __expf(z2);
    float r  = __fdividef(1.0f, e + 1.0f);
    return x - x * r;
}

// ---------------------------------------------------------------------------
// Edge kernel: warp per point, 256 threads (fastest measured config),
// two neighbors per iteration for reduction ILP.
// ---------------------------------------------------------------------------
__global__ void __launch_bounds__(256) edge_kernel(
    const float* __restrict__ g1, const float* __restrict__ be1,
    const float* __restrict__ W2, const float* __restrict__ b2)
{
    __shared__ float sW2[HID*COUT];   // 32KB
    int tid = threadIdx.x, lane = tid & 31, w = tid >> 5;
    for (int e = tid; e < HID*COUT; e += 256) sW2[e] = W2[e];
    __syncthreads();

    int p = blockIdx.x * 8 + w;
    int myidx = (lane < KNN) ? g_idx[p*KNN + lane] : 0;
    int c = lane * 4;

    float4 P4  = *(const float4*)&g_p[p*HID + c];
    float4 g1v = *(const float4*)&g1[c];
    float4 bev = *(const float4*)&be1[c];

    float4 accG = make_float4(0.f,0.f,0.f,0.f);

    int nb0 = __shfl_sync(FULLM, myidx, 0);
    int nb1 = __shfl_sync(FULLM, myidx, 1);
    float4 qa = __ldg((const float4*)&g_q[nb0*HID + c]);
    float4 qb = __ldg((const float4*)&g_q[nb1*HID + c]);

#pragma unroll
    for (int n = 0; n < KNN; n += 2) {
        float4 h0, h1;
        h0.x = qa.x + P4.x; h0.y = qa.y + P4.y; h0.z = qa.z + P4.z; h0.w = qa.w + P4.w;
        h1.x = qb.x + P4.x; h1.y = qb.y + P4.y; h1.z = qb.z + P4.z; h1.w = qb.w + P4.w;
        if (n + 2 < KNN) {
            int na  = __shfl_sync(FULLM, myidx, n+2);
            int nbx = __shfl_sync(FULLM, myidx, n+3);
            qa = __ldg((const float4*)&g_q[na*HID + c]);
            qb = __ldg((const float4*)&g_q[nbx*HID + c]);
        }
        float s0  = (h0.x + h0.y) + (h0.z + h0.w);
        float s20 = fmaf(h0.x,h0.x, fmaf(h0.y,h0.y, fmaf(h0.z,h0.z, h0.w*h0.w)));
        float s1  = (h1.x + h1.y) + (h1.z + h1.w);
        float s21 = fmaf(h1.x,h1.x, fmaf(h1.y,h1.y, fmaf(h1.z,h1.z, h1.w*h1.w)));
#pragma unroll
        for (int off = 16; off; off >>= 1) {
            s0  += __shfl_xor_sync(FULLM, s0,  off);
            s1  += __shfl_xor_sync(FULLM, s1,  off);
            s20 += __shfl_xor_sync(FULLM, s20, off);
            s21 += __shfl_xor_sync(FULLM, s21, off);
        }
        float mu0  = s0  * (1.f/HID);
        float var0 = s20 * (1.f/HID) - mu0*mu0;
        float rs0  = rsqrtf(var0 + 1e-5f);
        float mu1  = s1  * (1.f/HID);
        float var1 = s21 * (1.f/HID) - mu1*mu1;
        float rs1  = rsqrtf(var1 + 1e-5f);
        accG.x += gelu_fast(fmaf((h0.x - mu0)*rs0, g1v.x, bev.x));
        accG.y += gelu_fast(fmaf((h0.y - mu0)*rs0, g1v.y, bev.y));
        accG.z += gelu_fast(fmaf((h0.z - mu0)*rs0, g1v.z, bev.z));
        accG.w += gelu_fast(fmaf((h0.w - mu0)*rs0, g1v.w, bev.w));
        accG.x += gelu_fast(fmaf((h1.x - mu1)*rs1, g1v.x, bev.x));
        accG.y += gelu_fast(fmaf((h1.y - mu1)*rs1, g1v.y, bev.y));
        accG.z += gelu_fast(fmaf((h1.z - mu1)*rs1, g1v.z, bev.z));
        accG.w += gelu_fast(fmaf((h1.w - mu1)*rs1, g1v.w, bev.w));
    }
    accG.x *= (1.f/KNN); accG.y *= (1.f/KNN);
    accG.z *= (1.f/KNN); accG.w *= (1.f/KNN);

    // fused mid = G @ W2 + b2  (lane handles cols lane, lane+32)
    float m0 = __ldg(&b2[lane]);
    float m1 = __ldg(&b2[lane + 32]);
#pragma unroll
    for (int src = 0; src < 32; src++) {
        float gx = __shfl_sync(FULLM, accG.x, src);
        float gy = __shfl_sync(FULLM, accG.y, src);
        float gz = __shfl_sync(FULLM, accG.z, src);
        float gw = __shfl_sync(FULLM, accG.w, src);
        int k0 = src * 4;
        m0 = fmaf(gx, sW2[(k0+0)*COUT + lane], m0);
        m0 = fmaf(gy, sW2[(k0+1)*COUT + lane], m0);
        m0 = fmaf(gz, sW2[(k0+2)*COUT + lane], m0);
        m0 = fmaf(gw, sW2[(k0+3)*COUT + lane], m0);
        m1 = fmaf(gx, sW2[(k0+0)*COUT + lane + 32], m1);
        m1 = fmaf(gy, sW2[(k0+1)*COUT + lane + 32], m1);
        m1 = fmaf(gz, sW2[(k0+2)*COUT + lane + 32], m1);
        m1 = fmaf(gw, sW2[(k0+3)*COUT + lane + 32], m1);
    }
    g_mid[p*COUT + lane]      = m0;
    g_mid[p*COUT + lane + 32] = m1;
}

// ---------------------------------------------------------------------------
// MLP2 fused: 64 points per block, grid 256.
// ---------------------------------------------------------------------------
#define M2PTS 64
#define SMEM2_FLOATS (COUT*M2PTS + COUT*HID + HID*COUT)  // 20480

__global__ void __launch_bounds__(256, 2) mlp2_kernel(
    const float* __restrict__ Wo1, const float* __restrict__ bo1,
    const float* __restrict__ go,  const float* __restrict__ beo,
    const float* __restrict__ Wo2, const float* __restrict__ bo2,
    float* __restrict__ out)
{
    extern __shared__ float sm[];
    float* sAt  = sm;
    float* sWo1 = sm + COUT*M2PTS;
    float* sH   = sm;                          // aliases sAt+sWo1
    float* sWo2 = sm + COUT*M2PTS + COUT*HID;

    int tid = threadIdx.x;
    int r0  = blockIdx.x * M2PTS;

    for (int e = tid; e < COUT*HID; e += 256) sWo1[e] = Wo1[e];
    for (int e = tid; e < HID*COUT; e += 256) sWo2[e] = Wo2[e];
    for (int e = tid; e < COUT*M2PTS; e += 256) {
        int r = e & (M2PTS-1), k = e >> 6;
        sAt[k*M2PTS + r] = g_mid[(r0 + r)*COUT + k];
    }
    __syncthreads();

    int tx = tid & 15, ty = tid >> 4;

    float acc[4][8];
#pragma unroll
    for (int i = 0; i < 4; i++)
#pragma unroll
        for (int j = 0; j < 8; j++) acc[i][j] = 0.f;

    for (int k = 0; k < COUT; k++) {
        float4 a4 = *(const float4*)&sAt[k*M2PTS + ty*4];
        float4 c0 = *(const float4*)&sWo1[k*HID + tx*8];
        float4 c1 = *(const float4*)&sWo1[k*HID + tx*8 + 4];
        float a[4] = {a4.x,a4.y,a4.z,a4.w};
        float wv[8] = {c0.x,c0.y,c0.z,c0.w,c1.x,c1.y,c1.z,c1.w};
#pragma unroll
        for (int i = 0; i < 4; i++)
#pragma unroll
            for (int j = 0; j < 8; j++)
                acc[i][j] = fmaf(a[i], wv[j], acc[i][j]);
    }

    __syncthreads();

    float b1j[8], gj[8], bej[8];
#pragma unroll
    for (int j = 0; j < 8; j++) {
        int col = tx*8 + j;
        b1j[j] = bo1[col]; gj[j] = go[col]; bej[j] = beo[col];
    }
#pragma unroll
    for (int i = 0; i < 4; i++) {
        float ps = 0.f, ps2 = 0.f;
#pragma unroll
        for (int j = 0; j < 8; j++) {
            float h = acc[i][j] + b1j[j];
            acc[i][j] = h;
            ps += h; ps2 = fmaf(h, h, ps2);
        }
#pragma unroll
        for (int off = 8; off; off >>= 1) {
            ps  += __shfl_xor_sync(FULLM, ps,  off);
            ps2 += __shfl_xor_sync(FULLM, ps2, off);
        }
        float mu  = ps  * (1.f/HID);
        float var = ps2 * (1.f/HID) - mu*mu;
        float rs  = rsqrtf(var + 1e-5f);
        float o[8];
#pragma unroll
        for (int j = 0; j < 8; j++)
            o[j] = gelu_fast(fmaf((acc[i][j] - mu)*rs, gj[j], bej[j]));
        int row = ty*4 + i;
        *(float4*)&sH[row*132 + tx*8]     = make_float4(o[0],o[1],o[2],o[3]);
        *(float4*)&sH[row*132 + tx*8 + 4] = make_float4(o[4],o[5],o[6],o[7]);
    }
    __syncthreads();

    float acc2[4][4];
#pragma unroll
    for (int i = 0; i < 4; i++)
#pragma unroll
        for (int j = 0; j < 4; j++) acc2[i][j] = 0.f;

    for (int k = 0; k < HID; k += 4) {
        float4 w0 = *(const float4*)&sWo2[(k+0)*COUT + tx*4];
        float4 w1 = *(const float4*)&sWo2[(k+1)*COUT + tx*4];
        float4 w2 = *(const float4*)&sWo2[(k+2)*COUT + tx*4];
        float4 w3 = *(const float4*)&sWo2[(k+3)*COUT + tx*4];
#pragma unroll
        for (int i = 0; i < 4; i++) {
            float4 av = *(const float4*)&sH[(ty*4+i)*132 + k];
            acc2[i][0] = fmaf(av.x, w0.x, fmaf(av.y, w1.x, fmaf(av.z, w2.x, fmaf(av.w, w3.x, acc2[i][0]))));
            acc2[i][1] = fmaf(av.x, w0.y, fmaf(av.y, w1.y, fmaf(av.z, w2.y, fmaf(av.w, w3.y, acc2[i][1]))));
            acc2[i][2] = fmaf(av.x, w0.z, fmaf(av.y, w1.z, fmaf(av.z, w2.z, fmaf(av.w, w3.z, acc2[i][2]))));
            acc2[i][3] = fmaf(av.x, w0.w, fmaf(av.y, w1.w, fmaf(av.z, w2.w, fmaf(av.w, w3.w, acc2[i][3]))));
        }
    }

    float b2j[4];
#pragma unroll
    for (int j = 0; j < 4; j++) b2j[j] = bo2[tx*4 + j];
#pragma unroll
    for (int i = 0; i < 4; i++) {
        int row = r0 + ty*4 + i;
#pragma unroll
        for (int j = 0; j < 4; j++)
            out[row*COUT + tx*4 + j] = acc2[i][j] + b2j[j];
    }
}

// ---------------------------------------------------------------------------
extern "C" void kernel_launch(void* const* d_in, const int* in_sizes, int n_in,
                              void* d_out, int out_size) {
    const float* verts = (const float*)d_in[0];
    const float* feat  = (const float*)d_in[1];
    const float* W1    = (const float*)d_in[2];
    const float* b1    = (const float*)d_in[3];
    const float* g1    = (const float*)d_in[4];
    const float* be1   = (const float*)d_in[5];
    const float* W2    = (const float*)d_in[6];
    const float* b2    = (const float*)d_in[7];
    const float* Wo1   = (const float*)d_in[8];
    const float* bo1   = (const float*)d_in[9];
    const float* go    = (const float*)d_in[10];
    const float* beo   = (const float*)d_in[11];
    const float* Wo2   = (const float*)d_in[12];
    const float* bo2   = (const float*)d_in[13];
    float* out = (float*)d_out;

    const int smem2 = SMEM2_FLOATS * 4;   // 81920
    cudaFuncSetAttribute(mlp2_kernel, cudaFuncAttributeMaxDynamicSharedMemorySize, smem2);

    prep_kernel<<<(TOT + 255)/256, 256>>>(verts);
    knn_kernel<<<TOT/16, 256>>>();                 // 2 queries per warp, frozen-th
    precomp_kernel<<<TOT/8, 256>>>(verts, feat, W1, b1);
    edge_kernel<<<TOT/8, 256>>>(g1, be1, W2, b2);
    mlp2_kernel<<<TOT/M2PTS, 256, smem2>>>(Wo1, bo1, go, beo, Wo2, bo2, out);
}

// round 10
// speedup vs baseline: 1.6941x; 1.0085x over previous
#include <cuda_runtime.h>
#include <math.h>

#define BN   2
#define NPTS 8192
#define KNN  16
#define CIN  32
#define EIN  67      // 32 + 32 + 3
#define HID  128
#define COUT 64
#define TOT  (BN*NPTS)
#define FULLM 0xffffffffu

// Scratch (no allocations allowed)
__device__ int    g_idx[TOT*KNN];          // GLOBAL neighbor indices
__device__ float  g_mid[TOT*COUT];
__device__ float4 g_vert4[TOT];
__device__ float  g_q[TOT*HID];            // Q[n] = feat@W1a + vert@W1c
__device__ float  g_p[TOT*HID];            // P[n] = feat@W1b + b1 - vert@W1c
__device__ float4 g_stat[TOT];             // (Sum Q, Sum Q^2, Sum P, Sum P^2)

// ---------------------------------------------------------------------------
__global__ void prep_kernel(const float* __restrict__ verts) {
    int i = blockIdx.x * blockDim.x + threadIdx.x;
    if (i < TOT) {
        float x = verts[i*3+0], y = verts[i*3+1], z = verts[i*3+2];
        g_vert4[i] = make_float4(x, y, z, x*x + y*y + z*z);
    }
}

// ---------------------------------------------------------------------------
// KNN: ONE warp per query (max warp count for latency hiding of the insert
// shuffle chains) + batch-frozen threshold (the sorted-queue insert is a
// no-op for values >= current max, so th is purely a work filter).
// ---------------------------------------------------------------------------
__global__ void __launch_bounds__(256) knn_kernel() {
    int tid  = threadIdx.x;
    int lane = tid & 31;
    int w    = tid >> 5;
    int gq   = blockIdx.x * 8 + w;
    int base = (gq >> 13) * NPTS;

    float4 qv = g_vert4[gq];
    float qx = qv.x, qy = qv.y, qz = qv.z, qs = qv.w;

    float key = 3.4e38f;
    int   idx = 0;

#pragma unroll 2
    for (int i = 0; i < NPTS/32; i++) {
        float4 c = g_vert4[base + i*32 + lane];
        float dot = fmaf(qx, c.x, fmaf(qy, c.y, qz*c.z));
        float d   = fmaf(-2.0f, dot, qs + c.w);
        float thb = __shfl_sync(FULLM, key, 15);   // frozen per batch
        unsigned mask = __ballot_sync(FULLM, d < thb);
        while (mask) {
            int src = __ffs(mask) - 1;
            mask &= mask - 1;
            float v  = __shfl_sync(FULLM, d, src);
            int   vi = i*32 + src;
            // unconditional sorted insert (no-op if v >= all keys)
            float pk = __shfl_up_sync(FULLM, key, 1);
            int   pi = __shfl_up_sync(FULLM, idx, 1);
            if (v < key) {
                if (lane > 0 && v < pk) { key = pk; idx = pi; }
                else                    { key = v;  idx = vi; }
            }
        }
    }

    if (lane < KNN) g_idx[gq*KNN + lane] = base + idx;
}

// ---------------------------------------------------------------------------
// Precompute Q[n], P[n] and their channel sums / sum-of-squares.
// ---------------------------------------------------------------------------
__global__ void __launch_bounds__(256) precomp_kernel(
    const float* __restrict__ verts, const float* __restrict__ feat,
    const float* __restrict__ W1, const float* __restrict__ b1)
{
    __shared__ float sW1[EIN*HID];   // 34.3KB
    int tid = threadIdx.x, lane = tid & 31, w = tid >> 5;
    for (int e = tid; e < EIN*HID; e += 256) sW1[e] = W1[e];
    __syncthreads();

    int p = blockIdx.x * 8 + w;
    float4 f4 = make_float4(0.f,0.f,0.f,0.f);
    if (lane < 8) f4 = *(const float4*)&feat[p*CIN + lane*4];
    float vx = verts[p*3+0], vy = verts[p*3+1], vz = verts[p*3+2];

    int c = lane*4;
    float4 q  = make_float4(0.f,0.f,0.f,0.f);
    float4 pp = *(const float4*)&b1[c];

#pragma unroll
    for (int src = 0; src < 8; src++) {
        float fx = __shfl_sync(FULLM, f4.x, src);
        float fy = __shfl_sync(FULLM, f4.y, src);
        float fz = __shfl_sync(FULLM, f4.z, src);
        float fw = __shfl_sync(FULLM, f4.w, src);
        float fv[4] = {fx, fy, fz, fw};
        int k0 = src*4;
#pragma unroll
        for (int kk = 0; kk < 4; kk++) {
            int k = k0 + kk;
            float4 wa = *(const float4*)&sW1[k*HID + c];          // W1a row k
            float4 wb = *(const float4*)&sW1[(CIN + k)*HID + c];  // W1b row k
            q.x  = fmaf(fv[kk], wa.x, q.x);  q.y  = fmaf(fv[kk], wa.y, q.y);
            q.z  = fmaf(fv[kk], wa.z, q.z);  q.w  = fmaf(fv[kk], wa.w, q.w);
            pp.x = fmaf(fv[kk], wb.x, pp.x); pp.y = fmaf(fv[kk], wb.y, pp.y);
            pp.z = fmaf(fv[kk], wb.z, pp.z); pp.w = fmaf(fv[kk], wb.w, pp.w);
        }
    }
    float vv[3] = {vx, vy, vz};
#pragma unroll
    for (int k = 0; k < 3; k++) {
        float4 wc = *(const float4*)&sW1[(2*CIN + k)*HID + c];
        q.x  = fmaf(vv[k],  wc.x, q.x);  q.y  = fmaf(vv[k],  wc.y, q.y);
        q.z  = fmaf(vv[k],  wc.z, q.z);  q.w  = fmaf(vv[k],  wc.w, q.w);
        pp.x = fmaf(-vv[k], wc.x, pp.x); pp.y = fmaf(-vv[k], wc.y, pp.y);
        pp.z = fmaf(-vv[k], wc.z, pp.z); pp.w = fmaf(-vv[k], wc.w, pp.w);
    }
    *(float4*)&g_q[p*HID + c] = q;
    *(float4*)&g_p[p*HID + c] = pp;

    // channel statistics (once per point; replaces per-edge sum butterflies)
    float sq  = (q.x + q.y) + (q.z + q.w);
    float sq2 = fmaf(q.x,q.x, fmaf(q.y,q.y, fmaf(q.z,q.z, q.w*q.w)));
    float sp  = (pp.x + pp.y) + (pp.z + pp.w);
    float sp2 = fmaf(pp.x,pp.x, fmaf(pp.y,pp.y, fmaf(pp.z,pp.z, pp.w*pp.w)));
#pragma unroll
    for (int off = 16; off; off >>= 1) {
        sq  += __shfl_xor_sync(FULLM, sq,  off);
        sq2 += __shfl_xor_sync(FULLM, sq2, off);
        sp  += __shfl_xor_sync(FULLM, sp,  off);
        sp2 += __shfl_xor_sync(FULLM, sp2, off);
    }
    if (lane == 0) g_stat[p] = make_float4(sq, sq2, sp, sp2);
}

// ---------------------------------------------------------------------------
__device__ __forceinline__ float gelu_fast(float x) {
    float z2 = 1.5957691216057308f * fmaf(0.044715f * x * x, x, x);
    float e  = __expf(z2);
    float r  = __fdividef(1.0f, e + 1.0f);
    return x - x * r;
}

// ---------------------------------------------------------------------------
// Edge kernel: warp per point. LN statistics via precomputed sums:
//   Sum h   = Sq[nb] + Sp[p]                      (pure lookup)
//   Sum h^2 = Sq2[nb] + 2*(Q[nb].P[p]) + Sp2[p]   (ONE dot-reduction per edge)
// -> one butterfly chain per edge instead of two.
// ---------------------------------------------------------------------------
__global__ void __launch_bounds__(256) edge_kernel(
    const float* __restrict__ g1, const float* __restrict__ be1,
    const float* __restrict__ W2, const float* __restrict__ b2)
{
    __shared__ float sW2[HID*COUT];   // 32KB
    int tid = threadIdx.x, lane = tid & 31, w = tid >> 5;
    for (int e = tid; e < HID*COUT; e += 256) sW2[e] = W2[e];
    __syncthreads();

    int p = blockIdx.x * 8 + w;
    int myidx = (lane < KNN) ? g_idx[p*KNN + lane] : 0;
    int c = lane * 4;

    float4 P4  = *(const float4*)&g_p[p*HID + c];
    float4 g1v = *(const float4*)&g1[c];
    float4 bev = *(const float4*)&be1[c];
    float4 stP = g_stat[p];                         // Sp = .z, Sp2 = .w
    float4 stN = __ldg(&g_stat[myidx]);             // Sq = .x, Sq2 = .y (lane<16)
    float sumn = stN.x + stP.z;                     // Sum h for lane's neighbor
    float bsqn = stN.y + stP.w;                     // Sq2 + Sp2

    float4 accG = make_float4(0.f,0.f,0.f,0.f);

    int nb0 = __shfl_sync(FULLM, myidx, 0);
    int nb1 = __shfl_sync(FULLM, myidx, 1);
    float4 qa = __ldg((const float4*)&g_q[nb0*HID + c]);
    float4 qb = __ldg((const float4*)&g_q[nb1*HID + c]);

#pragma unroll
    for (int n = 0; n < KNN; n += 2) {
        float4 h0, h1;
        h0.x = qa.x + P4.x; h0.y = qa.y + P4.y; h0.z = qa.z + P4.z; h0.w = qa.w + P4.w;
        h1.x = qb.x + P4.x; h1.y = qb.y + P4.y; h1.z = qb.z + P4.z; h1.w = qb.w + P4.w;
        // dot(Q[nb], P[p]) partials
        float dp0 = fmaf(qa.x,P4.x, fmaf(qa.y,P4.y, fmaf(qa.z,P4.z, qa.w*P4.w)));
        float dp1 = fmaf(qb.x,P4.x, fmaf(qb.y,P4.y, fmaf(qb.z,P4.z, qb.w*P4.w)));
        if (n + 2 < KNN) {
            int na  = __shfl_sync(FULLM, myidx, n+2);
            int nbx = __shfl_sync(FULLM, myidx, n+3);
            qa = __ldg((const float4*)&g_q[na*HID + c]);
            qb = __ldg((const float4*)&g_q[nbx*HID + c]);
        }
#pragma unroll
        for (int off = 16; off; off >>= 1) {
            dp0 += __shfl_xor_sync(FULLM, dp0, off);
            dp1 += __shfl_xor_sync(FULLM, dp1, off);
        }
        float sum0 = __shfl_sync(FULLM, sumn, n);
        float sum1 = __shfl_sync(FULLM, sumn, n+1);
        float bb0  = __shfl_sync(FULLM, bsqn, n);
        float bb1  = __shfl_sync(FULLM, bsqn, n+1);

        float mu0  = sum0 * (1.f/HID);
        float e20  = fmaf(2.0f, dp0, bb0) * (1.f/HID);
        float rs0  = rsqrtf(e20 - mu0*mu0 + 1e-5f);
        float mu1  = sum1 * (1.f/HID);
        float e21  = fmaf(2.0f, dp1, bb1) * (1.f/HID);
        float rs1  = rsqrtf(e21 - mu1*mu1 + 1e-5f);

        accG.x += gelu_fast(fmaf((h0.x - mu0)*rs0, g1v.x, bev.x));
        accG.y += gelu_fast(fmaf((h0.y - mu0)*rs0, g1v.y, bev.y));
        accG.z += gelu_fast(fmaf((h0.z - mu0)*rs0, g1v.z, bev.z));
        accG.w += gelu_fast(fmaf((h0.w - mu0)*rs0, g1v.w, bev.w));
        accG.x += gelu_fast(fmaf((h1.x - mu1)*rs1, g1v.x, bev.x));
        accG.y += gelu_fast(fmaf((h1.y - mu1)*rs1, g1v.y, bev.y));
        accG.z += gelu_fast(fmaf((h1.z - mu1)*rs1, g1v.z, bev.z));
        accG.w += gelu_fast(fmaf((h1.w - mu1)*rs1, g1v.w, bev.w));
    }
    accG.x *= (1.f/KNN); accG.y *= (1.f/KNN);
    accG.z *= (1.f/KNN); accG.w *= (1.f/KNN);

    // fused mid = G @ W2 + b2  (lane handles cols lane, lane+32)
    float m0 = __ldg(&b2[lane]);
    float m1 = __ldg(&b2[lane + 32]);
#pragma unroll
    for (int src = 0; src < 32; src++) {
        float gx = __shfl_sync(FULLM, accG.x, src);
        float gy = __shfl_sync(FULLM, accG.y, src);
        float gz = __shfl_sync(FULLM, accG.z, src);
        float gw = __shfl_sync(FULLM, accG.w, src);
        int k0 = src * 4;
        m0 = fmaf(gx, sW2[(k0+0)*COUT + lane], m0);
        m0 = fmaf(gy, sW2[(k0+1)*COUT + lane], m0);
        m0 = fmaf(gz, sW2[(k0+2)*COUT + lane], m0);
        m0 = fmaf(gw, sW2[(k0+3)*COUT + lane], m0);
        m1 = fmaf(gx, sW2[(k0+0)*COUT + lane + 32], m1);
        m1 = fmaf(gy, sW2[(k0+1)*COUT + lane + 32], m1);
        m1 = fmaf(gz, sW2[(k0+2)*COUT + lane + 32], m1);
        m1 = fmaf(gw, sW2[(k0+3)*COUT + lane + 32], m1);
    }
    g_mid[p*COUT + lane]      = m0;
    g_mid[p*COUT + lane + 32] = m1;
}

// ---------------------------------------------------------------------------
// MLP2 fused: 64 points per block, grid 256.
// ---------------------------------------------------------------------------
#define M2PTS 64
#define SMEM2_FLOATS (COUT*M2PTS + COUT*HID + HID*COUT)  // 20480

__global__ void __launch_bounds__(256, 2) mlp2_kernel(
    const float* __restrict__ Wo1, const float* __restrict__ bo1,
    const float* __restrict__ go,  const float* __restrict__ beo,
    const float* __restrict__ Wo2, const float* __restrict__ bo2,
    float* __restrict__ out)
{
    extern __shared__ float sm[];
    float* sAt  = sm;
    float* sWo1 = sm + COUT*M2PTS;
    float* sH   = sm;                          // aliases sAt+sWo1
    float* sWo2 = sm + COUT*M2PTS + COUT*HID;

    int tid = threadIdx.x;
    int r0  = blockIdx.x * M2PTS;

    for (int e = tid; e < COUT*HID; e += 256) sWo1[e] = Wo1[e];
    for (int e = tid; e < HID*COUT; e += 256) sWo2[e] = Wo2[e];
    for (int e = tid; e < COUT*M2PTS; e += 256) {
        int r = e & (M2PTS-1), k = e >> 6;
        sAt[k*M2PTS + r] = g_mid[(r0 + r)*COUT + k];
    }
    __syncthreads();

    int tx = tid & 15, ty = tid >> 4;

    float acc[4][8];
#pragma unroll
    for (int i = 0; i < 4; i++)
#pragma unroll
        for (int j = 0; j < 8; j++) acc[i][j] = 0.f;

    for (int k = 0; k < COUT; k++) {
        float4 a4 = *(const float4*)&sAt[k*M2PTS + ty*4];
        float4 c0 = *(const float4*)&sWo1[k*HID + tx*8];
        float4 c1 = *(const float4*)&sWo1[k*HID + tx*8 + 4];
        float a[4] = {a4.x,a4.y,a4.z,a4.w};
        float wv[8] = {c0.x,c0.y,c0.z,c0.w,c1.x,c1.y,c1.z,c1.w};
#pragma unroll
        for (int i = 0; i < 4; i++)
#pragma unroll
            for (int j = 0; j < 8; j++)
                acc[i][j] = fmaf(a[i], wv[j], acc[i][j]);
    }

    __syncthreads();

    float b1j[8], gj[8], bej[8];
#pragma unroll
    for (int j = 0; j < 8; j++) {
        int col = tx*8 + j;
        b1j[j] = bo1[col]; gj[j] = go[col]; bej[j] = beo[col];
    }
#pragma unroll
    for (int i = 0; i < 4; i++) {
        float ps = 0.f, ps2 = 0.f;
#pragma unroll
        for (int j = 0; j < 8; j++) {
            float h = acc[i][j] + b1j[j];
            acc[i][j] = h;
            ps += h; ps2 = fmaf(h, h, ps2);
        }
#pragma unroll
        for (int off = 8; off; off >>= 1) {
            ps  += __shfl_xor_sync(FULLM, ps,  off);
            ps2 += __shfl_xor_sync(FULLM, ps2, off);
        }
        float mu  = ps  * (1.f/HID);
        float var = ps2 * (1.f/HID) - mu*mu;
        float rs  = rsqrtf(var + 1e-5f);
        float o[8];
#pragma unroll
        for (int j = 0; j < 8; j++)
            o[j] = gelu_fast(fmaf((acc[i][j] - mu)*rs, gj[j], bej[j]));
        int row = ty*4 + i;
        *(float4*)&sH[row*132 + tx*8]     = make_float4(o[0],o[1],o[2],o[3]);
        *(float4*)&sH[row*132 + tx*8 + 4] = make_float4(o[4],o[5],o[6],o[7]);
    }
    __syncthreads();

    float acc2[4][4];
#pragma unroll
    for (int i = 0; i < 4; i++)
#pragma unroll
        for (int j = 0; j < 4; j++) acc2[i][j] = 0.f;

    for (int k = 0; k < HID; k += 4) {
        float4 w0 = *(const float4*)&sWo2[(k+0)*COUT + tx*4];
        float4 w1 = *(const float4*)&sWo2[(k+1)*COUT + tx*4];
        float4 w2 = *(const float4*)&sWo2[(k+2)*COUT + tx*4];
        float4 w3 = *(const float4*)&sWo2[(k+3)*COUT + tx*4];
#pragma unroll
        for (int i = 0; i < 4; i++) {
            float4 av = *(const float4*)&sH[(ty*4+i)*132 + k];
            acc2[i][0] = fmaf(av.x, w0.x, fmaf(av.y, w1.x, fmaf(av.z, w2.x, fmaf(av.w, w3.x, acc2[i][0]))));
            acc2[i][1] = fmaf(av.x, w0.y, fmaf(av.y, w1.y, fmaf(av.z, w2.y, fmaf(av.w, w3.y, acc2[i][1]))));
            acc2[i][2] = fmaf(av.x, w0.z, fmaf(av.y, w1.z, fmaf(av.z, w2.z, fmaf(av.w, w3.z, acc2[i][2]))));
            acc2[i][3] = fmaf(av.x, w0.w, fmaf(av.y, w1.w, fmaf(av.z, w2.w, fmaf(av.w, w3.w, acc2[i][3]))));
        }
    }

    float b2j[4];
#pragma unroll
    for (int j = 0; j < 4; j++) b2j[j] = bo2[tx*4 + j];
#pragma unroll
    for (int i = 0; i < 4; i++) {
        int row = r0 + ty*4 + i;
#pragma unroll
        for (int j = 0; j < 4; j++)
            out[row*COUT + tx*4 + j] = acc2[i][j] + b2j[j];
    }
}

// ---------------------------------------------------------------------------
extern "C" void kernel_launch(void* const* d_in, const int* in_sizes, int n_in,
                              void* d_out, int out_size) {
    const float* verts = (const float*)d_in[0];
    const float* feat  = (const float*)d_in[1];
    const float* W1    = (const float*)d_in[2];
    const float* b1    = (const float*)d_in[3];
    const float* g1    = (const float*)d_in[4];
    const float* be1   = (const float*)d_in[5];
    const float* W2    = (const float*)d_in[6];
    const float* b2    = (const float*)d_in[7];
    const float* Wo1   = (const float*)d_in[8];
    const float* bo1   = (const float*)d_in[9];
    const float* go    = (const float*)d_in[10];
    const float* beo   = (const float*)d_in[11];
    const float* Wo2   = (const float*)d_in[12];
    const float* bo2   = (const float*)d_in[13];
    float* out = (float*)d_out;

    const int smem2 = SMEM2_FLOATS * 4;   // 81920
    cudaFuncSetAttribute(mlp2_kernel, cudaFuncAttributeMaxDynamicSharedMemorySize, smem2);

    prep_kernel<<<(TOT + 255)/256, 256>>>(verts);
    knn_kernel<<<TOT/8, 256>>>();                  // 1 query per warp, frozen-th
    precomp_kernel<<<TOT/8, 256>>>(verts, feat, W1, b1);
    edge_kernel<<<TOT/8, 256>>>(g1, be1, W2, b2);
    mlp2_kernel<<<TOT/M2PTS, 256, smem2>>>(Wo1, bo1, go, beo, Wo2, bo2, out);
}

// round 11
// speedup vs baseline: 1.7481x; 1.0319x over previous
#include <cuda_runtime.h>
#include <math.h>

#define BN   2
#define NPTS 8192
#define KNN  16
#define CIN  32
#define EIN  67      // 32 + 32 + 3
#define HID  128
#define COUT 64
#define TOT  (BN*NPTS)
#define FULLM 0xffffffffu
#define FMAX  3.402823466e38f

// x-bucket sort for KNN
#define NB    512
#define XMIN  (-4.65f)
#define XSPAN 9.3f
#define BW    (XSPAN/NB)
#define INVBW (NB/XSPAN)
#define EXPB  2

// Scratch (no allocations allowed)
__device__ int    g_idx[TOT*KNN];          // GLOBAL neighbor indices
__device__ float  g_mid[TOT*COUT];
__device__ float4 g_vert4[TOT];
__device__ float  g_q[TOT*HID];            // Q[n] = feat@W1a + vert@W1c
__device__ float  g_p[TOT*HID];            // P[n] = feat@W1b + b1 - vert@W1c
__device__ float4 g_stat[TOT];             // (Sum Q, Sum Q^2, Sum P, Sum P^2)
__device__ int    g_bcount[BN][NB];
__device__ int    g_bstart[BN][NB+1];
__device__ int    g_bcur[BN][NB];
__device__ float4 g_sx4[TOT];              // x-sorted points (per batch)
__device__ int    g_ssid[TOT];             // sorted -> original GLOBAL index

// ---------------------------------------------------------------------------
__global__ void prep_kernel(const float* __restrict__ verts) {
    int i = blockIdx.x * blockDim.x + threadIdx.x;
    if (i < TOT) {
        float x = verts[i*3+0], y = verts[i*3+1], z = verts[i*3+2];
        g_vert4[i] = make_float4(x, y, z, x*x + y*y + z*z);
    }
    if (i < BN*NB) ((int*)g_bcount)[i] = 0;
}

__device__ __forceinline__ int clampi(int v, int lo, int hi) {
    return v < lo ? lo : (v > hi ? hi : v);
}

__global__ void bin_kernel(const float* __restrict__ verts) {
    int i = blockIdx.x * blockDim.x + threadIdx.x;
    if (i >= TOT) return;
    int bkt = clampi((int)((verts[i*3] - XMIN) * INVBW), 0, NB-1);
    atomicAdd(&g_bcount[i >> 13][bkt], 1);
}

// 512-wide Hillis-Steele scan, one block per batch (fast, unlike a serial scan)
__global__ void scanb_kernel() {
    __shared__ int s[NB];
    int bb = blockIdx.x, t = threadIdx.x;
    int v = g_bcount[bb][t];
    s[t] = v;
    __syncthreads();
    for (int d = 1; d < NB; d <<= 1) {
        int u = (t >= d) ? s[t - d] : 0;
        __syncthreads();
        s[t] += u;
        __syncthreads();
    }
    g_bstart[bb][t] = s[t] - v;
    g_bcur[bb][t]   = s[t] - v;
    if (t == NB-1) g_bstart[bb][NB] = NPTS;
}

__global__ void scatter_kernel() {
    int i = blockIdx.x * blockDim.x + threadIdx.x;
    if (i >= TOT) return;
    float4 v = g_vert4[i];
    int bb  = i >> 13;
    int bkt = clampi((int)((v.x - XMIN) * INVBW), 0, NB-1);
    int slot = bb * NPTS + atomicAdd(&g_bcur[bb][bkt], 1);
    g_sx4[slot]  = v;
    g_ssid[slot] = i;
}

// ---------------------------------------------------------------------------
// Scan sorted segment [a,b) through the warp's ascending lane-sorted best-32
// queue (batch-frozen threshold; identical distance formula as brute force).
// idx holds SORTED positions (mapped to original at the end).
// ---------------------------------------------------------------------------
__device__ __forceinline__ void scan_seg(int a, int b, int sbase, float4 qv,
                                         int lane, float& key, int& idx) {
    for (int i = a; i < b; i += 32) {
        int j = i + lane;
        float d = FMAX;
        if (j < b) {
            float4 c = __ldg(&g_sx4[sbase + j]);
            float dot = fmaf(qv.x, c.x, fmaf(qv.y, c.y, qv.z*c.z));
            d = fmaf(-2.0f, dot, qv.w + c.w);
        }
        float thb = __shfl_sync(FULLM, key, 15);
        unsigned mask = __ballot_sync(FULLM, d < thb);
        while (mask) {
            int src = __ffs(mask) - 1;
            mask &= mask - 1;
            float v  = __shfl_sync(FULLM, d, src);
            int   vi = i + src;
            float pk = __shfl_up_sync(FULLM, key, 1);
            int   pi = __shfl_up_sync(FULLM, idx, 1);
            if (v < key) {
                if (lane > 0 && v < pk) { key = pk; idx = pi; }
                else                    { key = v;  idx = vi; }
            }
        }
    }
}

// ---------------------------------------------------------------------------
// KNN: warp per query over the x-sorted array. Expand the contiguous window
// outward (2 buckets a side per step, cheaper side first) until the EXACT
// bound holds: every unscanned point has |x-qx| >= boundary gap, so
// d16 <= gap^2 proves no unscanned point can enter the top-16.
// ---------------------------------------------------------------------------
__global__ void __launch_bounds__(256) knn_kernel() {
    int tid  = threadIdx.x;
    int lane = tid & 31;
    int w    = tid >> 5;
    int gq   = blockIdx.x * 8 + w;
    int bb   = gq >> 13;
    int sbase = bb * NPTS;

    float4 qv = g_vert4[gq];
    int b0 = clampi((int)((qv.x - XMIN) * INVBW), 0, NB-1);
    const int* bst = g_bstart[bb];

    int lo = b0, hi = b0;
    int curL = bst[b0], curR = bst[b0+1];
    float key = FMAX;
    int   idx = 0;

    scan_seg(curL, curR, sbase, qv, lane, key, idx);

    for (;;) {
        float dxL = (lo == 0)      ? FMAX : qv.x - (XMIN + lo * BW);
        float dxR = (hi == NB - 1) ? FMAX : (XMIN + (hi + 1) * BW) - qv.x;
        float bnd = fminf(dxL, dxR);
        if (bnd > 1e37f) break;                    // everything scanned
        float th = __shfl_sync(FULLM, key, 15);
        if (th <= bnd * bnd) break;                // exact stop bound
        if (dxL <= dxR) {
            int nlo = max(0, lo - EXPB);
            int nL  = bst[nlo];
            scan_seg(nL, curL, sbase, qv, lane, key, idx);
            curL = nL; lo = nlo;
        } else {
            int nhi = min(NB - 1, hi + EXPB);
            int nR  = bst[nhi + 1];
            scan_seg(curR, nR, sbase, qv, lane, key, idx);
            curR = nR; hi = nhi;
        }
    }

    if (lane < KNN) g_idx[gq*KNN + lane] = g_ssid[sbase + idx];
}

// ---------------------------------------------------------------------------
// Precompute Q[n], P[n] and their channel sums / sum-of-squares.
// ---------------------------------------------------------------------------
__global__ void __launch_bounds__(256) precomp_kernel(
    const float* __restrict__ verts, const float* __restrict__ feat,
    const float* __restrict__ W1, const float* __restrict__ b1)
{
    __shared__ float sW1[EIN*HID];   // 34.3KB
    int tid = threadIdx.x, lane = tid & 31, w = tid >> 5;
    for (int e = tid; e < EIN*HID; e += 256) sW1[e] = W1[e];
    __syncthreads();

    int p = blockIdx.x * 8 + w;
    float4 f4 = make_float4(0.f,0.f,0.f,0.f);
    if (lane < 8) f4 = *(const float4*)&feat[p*CIN + lane*4];
    float vx = verts[p*3+0], vy = verts[p*3+1], vz = verts[p*3+2];

    int c = lane*4;
    float4 q  = make_float4(0.f,0.f,0.f,0.f);
    float4 pp = *(const float4*)&b1[c];

#pragma unroll
    for (int src = 0; src < 8; src++) {
        float fx = __shfl_sync(FULLM, f4.x, src);
        float fy = __shfl_sync(FULLM, f4.y, src);
        float fz = __shfl_sync(FULLM, f4.z, src);
        float fw = __shfl_sync(FULLM, f4.w, src);
        float fv[4] = {fx, fy, fz, fw};
        int k0 = src*4;
#pragma unroll
        for (int kk = 0; kk < 4; kk++) {
            int k = k0 + kk;
            float4 wa = *(const float4*)&sW1[k*HID + c];          // W1a row k
            float4 wb = *(const float4*)&sW1[(CIN + k)*HID + c];  // W1b row k
            q.x  = fmaf(fv[kk], wa.x, q.x);  q.y  = fmaf(fv[kk], wa.y, q.y);
            q.z  = fmaf(fv[kk], wa.z, q.z);  q.w  = fmaf(fv[kk], wa.w, q.w);
            pp.x = fmaf(fv[kk], wb.x, pp.x); pp.y = fmaf(fv[kk], wb.y, pp.y);
            pp.z = fmaf(fv[kk], wb.z, pp.z); pp.w = fmaf(fv[kk], wb.w, pp.w);
        }
    }
    float vv[3] = {vx, vy, vz};
#pragma unroll
    for (int k = 0; k < 3; k++) {
        float4 wc = *(const float4*)&sW1[(2*CIN + k)*HID + c];
        q.x  = fmaf(vv[k],  wc.x, q.x);  q.y  = fmaf(vv[k],  wc.y, q.y);
        q.z  = fmaf(vv[k],  wc.z, q.z);  q.w  = fmaf(vv[k],  wc.w, q.w);
        pp.x = fmaf(-vv[k], wc.x, pp.x); pp.y = fmaf(-vv[k], wc.y, pp.y);
        pp.z = fmaf(-vv[k], wc.z, pp.z); pp.w = fmaf(-vv[k], wc.w, pp.w);
    }
    *(float4*)&g_q[p*HID + c] = q;
    *(float4*)&g_p[p*HID + c] = pp;

    float sq  = (q.x + q.y) + (q.z + q.w);
    float sq2 = fmaf(q.x,q.x, fmaf(q.y,q.y, fmaf(q.z,q.z, q.w*q.w)));
    float sp  = (pp.x + pp.y) + (pp.z + pp.w);
    float sp2 = fmaf(pp.x,pp.x, fmaf(pp.y,pp.y, fmaf(pp.z,pp.z, pp.w*pp.w)));
#pragma unroll
    for (int off = 16; off; off >>= 1) {
        sq  += __shfl_xor_sync(FULLM, sq,  off);
        sq2 += __shfl_xor_sync(FULLM, sq2, off);
        sp  += __shfl_xor_sync(FULLM, sp,  off);
        sp2 += __shfl_xor_sync(FULLM, sp2, off);
    }
    if (lane == 0) g_stat[p] = make_float4(sq, sq2, sp, sp2);
}

// ---------------------------------------------------------------------------
__device__ __forceinline__ float gelu_fast(float x) {
    float z2 = 1.5957691216057308f * fmaf(0.044715f * x * x, x, x);
    float e  = __expf(z2);
    float r  = __fdividef(1.0f, e + 1.0f);
    return x - x * r;
}

// ---------------------------------------------------------------------------
// Edge kernel: warp per point. LN stats via precomputed sums; one
// dot-reduction per edge.
// ---------------------------------------------------------------------------
__global__ void __launch_bounds__(256) edge_kernel(
    const float* __restrict__ g1, const float* __restrict__ be1,
    const float* __restrict__ W2, const float* __restrict__ b2)
{
    __shared__ float sW2[HID*COUT];   // 32KB
    int tid = threadIdx.x, lane = tid & 31, w = tid >> 5;
    for (int e = tid; e < HID*COUT; e += 256) sW2[e] = W2[e];
    __syncthreads();

    int p = blockIdx.x * 8 + w;
    int myidx = (lane < KNN) ? g_idx[p*KNN + lane] : 0;
    int c = lane * 4;

    float4 P4  = *(const float4*)&g_p[p*HID + c];
    float4 g1v = *(const float4*)&g1[c];
    float4 bev = *(const float4*)&be1[c];
    float4 stP = g_stat[p];
    float4 stN = __ldg(&g_stat[myidx]);
    float sumn = stN.x + stP.z;
    float bsqn = stN.y + stP.w;

    float4 accG = make_float4(0.f,0.f,0.f,0.f);

    int nb0 = __shfl_sync(FULLM, myidx, 0);
    int nb1 = __shfl_sync(FULLM, myidx, 1);
    float4 qa = __ldg((const float4*)&g_q[nb0*HID + c]);
    float4 qb = __ldg((const float4*)&g_q[nb1*HID + c]);

#pragma unroll
    for (int n = 0; n < KNN; n += 2) {
        float4 h0, h1;
        h0.x = qa.x + P4.x; h0.y = qa.y + P4.y; h0.z = qa.z + P4.z; h0.w = qa.w + P4.w;
        h1.x = qb.x + P4.x; h1.y = qb.y + P4.y; h1.z = qb.z + P4.z; h1.w = qb.w + P4.w;
        float dp0 = fmaf(qa.x,P4.x, fmaf(qa.y,P4.y, fmaf(qa.z,P4.z, qa.w*P4.w)));
        float dp1 = fmaf(qb.x,P4.x, fmaf(qb.y,P4.y, fmaf(qb.z,P4.z, qb.w*P4.w)));
        if (n + 2 < KNN) {
            int na  = __shfl_sync(FULLM, myidx, n+2);
            int nbx = __shfl_sync(FULLM, myidx, n+3);
            qa = __ldg((const float4*)&g_q[na*HID + c]);
            qb = __ldg((const float4*)&g_q[nbx*HID + c]);
        }
#pragma unroll
        for (int off = 16; off; off >>= 1) {
            dp0 += __shfl_xor_sync(FULLM, dp0, off);
            dp1 += __shfl_xor_sync(FULLM, dp1, off);
        }
        float sum0 = __shfl_sync(FULLM, sumn, n);
        float sum1 = __shfl_sync(FULLM, sumn, n+1);
        float bb0  = __shfl_sync(FULLM, bsqn, n);
        float bb1  = __shfl_sync(FULLM, bsqn, n+1);

        float mu0 = sum0 * (1.f/HID);
        float e20 = fmaf(2.0f, dp0, bb0) * (1.f/HID);
        float rs0 = rsqrtf(e20 - mu0*mu0 + 1e-5f);
        float mu1 = sum1 * (1.f/HID);
        float e21 = fmaf(2.0f, dp1, bb1) * (1.f/HID);
        float rs1 = rsqrtf(e21 - mu1*mu1 + 1e-5f);

        accG.x += gelu_fast(fmaf((h0.x - mu0)*rs0, g1v.x, bev.x));
        accG.y += gelu_fast(fmaf((h0.y - mu0)*rs0, g1v.y, bev.y));
        accG.z += gelu_fast(fmaf((h0.z - mu0)*rs0, g1v.z, bev.z));
        accG.w += gelu_fast(fmaf((h0.w - mu0)*rs0, g1v.w, bev.w));
        accG.x += gelu_fast(fmaf((h1.x - mu1)*rs1, g1v.x, bev.x));
        accG.y += gelu_fast(fmaf((h1.y - mu1)*rs1, g1v.y, bev.y));
        accG.z += gelu_fast(fmaf((h1.z - mu1)*rs1, g1v.z, bev.z));
        accG.w += gelu_fast(fmaf((h1.w - mu1)*rs1, g1v.w, bev.w));
    }
    accG.x *= (1.f/KNN); accG.y *= (1.f/KNN);
    accG.z *= (1.f/KNN); accG.w *= (1.f/KNN);

    float m0 = __ldg(&b2[lane]);
    float m1 = __ldg(&b2[lane + 32]);
#pragma unroll
    for (int src = 0; src < 32; src++) {
        float gx = __shfl_sync(FULLM, accG.x, src);
        float gy = __shfl_sync(FULLM, accG.y, src);
        float gz = __shfl_sync(FULLM, accG.z, src);
        float gw = __shfl_sync(FULLM, accG.w, src);
        int k0 = src * 4;
        m0 = fmaf(gx, sW2[(k0+0)*COUT + lane], m0);
        m0 = fmaf(gy, sW2[(k0+1)*COUT + lane], m0);
        m0 = fmaf(gz, sW2[(k0+2)*COUT + lane], m0);
        m0 = fmaf(gw, sW2[(k0+3)*COUT + lane], m0);
        m1 = fmaf(gx, sW2[(k0+0)*COUT + lane + 32], m1);
        m1 = fmaf(gy, sW2[(k0+1)*COUT + lane + 32], m1);
        m1 = fmaf(gz, sW2[(k0+2)*COUT + lane + 32], m1);
        m1 = fmaf(gw, sW2[(k0+3)*COUT + lane + 32], m1);
    }
    g_mid[p*COUT + lane]      = m0;
    g_mid[p*COUT + lane + 32] = m1;
}

// ---------------------------------------------------------------------------
// MLP2 fused: 64 points per block, grid 256.
// ---------------------------------------------------------------------------
#define M2PTS 64
#define SMEM2_FLOATS (COUT*M2PTS + COUT*HID + HID*COUT)  // 20480

__global__ void __launch_bounds__(256, 2) mlp2_kernel(
    const float* __restrict__ Wo1, const float* __restrict__ bo1,
    const float* __restrict__ go,  const float* __restrict__ beo,
    const float* __restrict__ Wo2, const float* __restrict__ bo2,
    float* __restrict__ out)
{
    extern __shared__ float sm[];
    float* sAt  = sm;
    float* sWo1 = sm + COUT*M2PTS;
    float* sH   = sm;                          // aliases sAt+sWo1
    float* sWo2 = sm + COUT*M2PTS + COUT*HID;

    int tid = threadIdx.x;
    int r0  = blockIdx.x * M2PTS;

    for (int e = tid; e < COUT*HID; e += 256) sWo1[e] = Wo1[e];
    for (int e = tid; e < HID*COUT; e += 256) sWo2[e] = Wo2[e];
    for (int e = tid; e < COUT*M2PTS; e += 256) {
        int r = e & (M2PTS-1), k = e >> 6;
        sAt[k*M2PTS + r] = g_mid[(r0 + r)*COUT + k];
    }
    __syncthreads();

    int tx = tid & 15, ty = tid >> 4;

    float acc[4][8];
#pragma unroll
    for (int i = 0; i < 4; i++)
#pragma unroll
        for (int j = 0; j < 8; j++) acc[i][j] = 0.f;

    for (int k = 0; k < COUT; k++) {
        float4 a4 = *(const float4*)&sAt[k*M2PTS + ty*4];
        float4 c0 = *(const float4*)&sWo1[k*HID + tx*8];
        float4 c1 = *(const float4*)&sWo1[k*HID + tx*8 + 4];
        float a[4] = {a4.x,a4.y,a4.z,a4.w};
        float wv[8] = {c0.x,c0.y,c0.z,c0.w,c1.x,c1.y,c1.z,c1.w};
#pragma unroll
        for (int i = 0; i < 4; i++)
#pragma unroll
            for (int j = 0; j < 8; j++)
                acc[i][j] = fmaf(a[i], wv[j], acc[i][j]);
    }

    __syncthreads();

    float b1j[8], gj[8], bej[8];
#pragma unroll
    for (int j = 0; j < 8; j++) {
        int col = tx*8 + j;
        b1j[j] = bo1[col]; gj[j] = go[col]; bej[j] = beo[col];
    }
#pragma unroll
    for (int i = 0; i < 4; i++) {
        float ps = 0.f, ps2 = 0.f;
#pragma unroll
        for (int j = 0; j < 8; j++) {
            float h = acc[i][j] + b1j[j];
            acc[i][j] = h;
            ps += h; ps2 = fmaf(h, h, ps2);
        }
#pragma unroll
        for (int off = 8; off; off >>= 1) {
            ps  += __shfl_xor_sync(FULLM, ps,  off);
            ps2 += __shfl_xor_sync(FULLM, ps2, off);
        }
        float mu  = ps  * (1.f/HID);
        float var = ps2 * (1.f/HID) - mu*mu;
        float rs  = rsqrtf(var + 1e-5f);
        float o[8];
#pragma unroll
        for (int j = 0; j < 8; j++)
            o[j] = gelu_fast(fmaf((acc[i][j] - mu)*rs, gj[j], bej[j]));
        int row = ty*4 + i;
        *(float4*)&sH[row*132 + tx*8]     = make_float4(o[0],o[1],o[2],o[3]);
        *(float4*)&sH[row*132 + tx*8 + 4] = make_float4(o[4],o[5],o[6],o[7]);
    }
    __syncthreads();

    float acc2[4][4];
#pragma unroll
    for (int i = 0; i < 4; i++)
#pragma unroll
        for (int j = 0; j < 4; j++) acc2[i][j] = 0.f;

    for (int k = 0; k < HID; k += 4) {
        float4 w0 = *(const float4*)&sWo2[(k+0)*COUT + tx*4];
        float4 w1 = *(const float4*)&sWo2[(k+1)*COUT + tx*4];
        float4 w2 = *(const float4*)&sWo2[(k+2)*COUT + tx*4];
        float4 w3 = *(const float4*)&sWo2[(k+3)*COUT + tx*4];
#pragma unroll
        for (int i = 0; i < 4; i++) {
            float4 av = *(const float4*)&sH[(ty*4+i)*132 + k];
            acc2[i][0] = fmaf(av.x, w0.x, fmaf(av.y, w1.x, fmaf(av.z, w2.x, fmaf(av.w, w3.x, acc2[i][0]))));
            acc2[i][1] = fmaf(av.x, w0.y, fmaf(av.y, w1.y, fmaf(av.z, w2.y, fmaf(av.w, w3.y, acc2[i][1]))));
            acc2[i][2] = fmaf(av.x, w0.z, fmaf(av.y, w1.z, fmaf(av.z, w2.z, fmaf(av.w, w3.z, acc2[i][2]))));
            acc2[i][3] = fmaf(av.x, w0.w, fmaf(av.y, w1.w, fmaf(av.z, w2.w, fmaf(av.w, w3.w, acc2[i][3]))));
        }
    }

    float b2j[4];
#pragma unroll
    for (int j = 0; j < 4; j++) b2j[j] = bo2[tx*4 + j];
#pragma unroll
    for (int i = 0; i < 4; i++) {
        int row = r0 + ty*4 + i;
#pragma unroll
        for (int j = 0; j < 4; j++)
            out[row*COUT + tx*4 + j] = acc2[i][j] + b2j[j];
    }
}

// ---------------------------------------------------------------------------
extern "C" void kernel_launch(void* const* d_in, const int* in_sizes, int n_in,
                              void* d_out, int out_size) {
    const float* verts = (const float*)d_in[0];
    const float* feat  = (const float*)d_in[1];
    const float* W1    = (const float*)d_in[2];
    const float* b1    = (const float*)d_in[3];
    const float* g1    = (const float*)d_in[4];
    const float* be1   = (const float*)d_in[5];
    const float* W2    = (const float*)d_in[6];
    const float* b2    = (const float*)d_in[7];
    const float* Wo1   = (const float*)d_in[8];
    const float* bo1   = (const float*)d_in[9];
    const float* go    = (const float*)d_in[10];
    const float* beo   = (const float*)d_in[11];
    const float* Wo2   = (const float*)d_in[12];
    const float* bo2   = (const float*)d_in[13];
    float* out = (float*)d_out;

    const int smem2 = SMEM2_FLOATS * 4;   // 81920
    cudaFuncSetAttribute(mlp2_kernel, cudaFuncAttributeMaxDynamicSharedMemorySize, smem2);

    prep_kernel<<<(TOT + 255)/256, 256>>>(verts);
    bin_kernel<<<(TOT + 255)/256, 256>>>(verts);
    scanb_kernel<<<BN, NB>>>();
    scatter_kernel<<<(TOT + 255)/256, 256>>>();
    knn_kernel<<<TOT/8, 256>>>();                  // warp/query over sorted window
    precomp_kernel<<<TOT/8, 256>>>(verts, feat, W1, b1);
    edge_kernel<<<TOT/8, 256>>>(g1, be1, W2, b2);
    mlp2_kernel<<<TOT/M2PTS, 256, smem2>>>(Wo1, bo1, go, beo, Wo2, bo2, out);
}